// round 4
// baseline (speedup 1.0000x reference)
#include <cuda_runtime.h>

// LabelLoss: out[b] = sum_{n,c<7} (pred[b,n,c] - gt[b,n,c])^2
// pred, gt: [256, 16384, 8] fp32. Pure HBM-bound streaming reduction.
//
// R4: same streaming kernel as R3 (fine-grained chunks, multi-wave HW
// work-stealing, coalesced float4, channel-7 parity mask) but partial sums
// go to a __device__ scratch via plain stores (no atomics, no zero-init
// kernel, no upstream dependency). A tiny second kernel reduces scratch
// into d_out (overwriting the 0xAA poison).

#define B_DIM       256
#define N_OBJ       16384
#define THREADS     256
#define SPLIT       32                        // chunks per batch row -> grid 8192
#define F4_PER_ROW  (N_OBJ * 2)               // 32768 float4 per batch row
#define F4_PER_BLK  (F4_PER_ROW / SPLIT)      // 1024 float4 per block (per stream)
#define UNROLL      4                         // THREADS*UNROLL == F4_PER_BLK

// Partial sums, laid out [s][b] so the reduce kernel reads coalesced.
__device__ float g_partials[SPLIT * B_DIM];

__global__ __launch_bounds__(THREADS, 8)
void label_loss_kernel(const float* __restrict__ pred,
                       const float* __restrict__ gt) {
    const int b = blockIdx.x;
    const int s = blockIdx.y;

    const float4* __restrict__ p =
        reinterpret_cast<const float4*>(pred) + (size_t)b * F4_PER_ROW + s * F4_PER_BLK;
    const float4* __restrict__ g =
        reinterpret_cast<const float4*>(gt)   + (size_t)b * F4_PER_ROW + s * F4_PER_BLK;

    // float4-index parity for this thread is constant (strides even):
    // odd float4 -> its .w is channel 7 (excluded from loss).
    const float wsel = (threadIdx.x & 1) ? 0.0f : 1.0f;

    // One fully-unrolled pass: 4 p + 4 g = 8 front-batched LDG.128 per thread.
    float4 pv[UNROLL], gv[UNROLL];
    #pragma unroll
    for (int u = 0; u < UNROLL; u++) {
        const int idx = u * THREADS + threadIdx.x;
        pv[u] = p[idx];
        gv[u] = g[idx];
    }

    float acc = 0.0f;
    #pragma unroll
    for (int u = 0; u < UNROLL; u++) {
        float d0 = pv[u].x - gv[u].x;
        float d1 = pv[u].y - gv[u].y;
        float d2 = pv[u].z - gv[u].z;
        float d3 = (pv[u].w - gv[u].w) * wsel;   // channel 7 masked on odd lanes
        acc += d0*d0 + d1*d1 + d2*d2 + d3*d3;
    }

    // Warp reduction
    #pragma unroll
    for (int off = 16; off > 0; off >>= 1)
        acc += __shfl_xor_sync(0xFFFFFFFFu, acc, off);

    // Cross-warp reduction via shared memory
    __shared__ float warp_sums[THREADS / 32];
    const int lane = threadIdx.x & 31;
    const int wid  = threadIdx.x >> 5;
    if (lane == 0) warp_sums[wid] = acc;
    __syncthreads();

    if (wid == 0) {
        float v = (lane < THREADS / 32) ? warp_sums[lane] : 0.0f;
        #pragma unroll
        for (int off = 4; off > 0; off >>= 1)
            v += __shfl_xor_sync(0xFFFFFFFFu, v, off);
        if (lane == 0)
            g_partials[s * B_DIM + b] = v;   // plain store, no atomic
    }
}

__global__ void reduce_partials_kernel(float* __restrict__ out) {
    const int b = threadIdx.x;               // 256 threads, one per batch
    float acc = 0.0f;
    #pragma unroll
    for (int s = 0; s < SPLIT; s++)
        acc += g_partials[s * B_DIM + b];    // coalesced across threads
    out[b] = acc;
}

extern "C" void kernel_launch(void* const* d_in, const int* in_sizes, int n_in,
                              void* d_out, int out_size) {
    const float* pred = (const float*)d_in[0];
    const float* gt   = (const float*)d_in[1];
    float* out        = (float*)d_out;

    dim3 grid(B_DIM, SPLIT);
    label_loss_kernel<<<grid, THREADS>>>(pred, gt);
    reduce_partials_kernel<<<1, B_DIM>>>(out);
}

// round 5
// speedup vs baseline: 1.0358x; 1.0358x over previous
#include <cuda_runtime.h>

// LabelLoss: out[b] = sum_{n,c<7} (pred[b,n,c] - gt[b,n,c])^2
// pred, gt: [256, 16384, 8] fp32. Pure HBM-bound streaming reduction.
//
// R5: R4's two-kernel no-atomic scheme, but the epilogue is parallelized:
// partials stored [b][s], reduced by one warp per batch (256 warps across
// 32 blocks) with coalesced L2-hit loads + shuffle reduce.

#define B_DIM       256
#define N_OBJ       16384
#define THREADS     256
#define SPLIT       32                        // chunks per batch row -> grid 8192
#define F4_PER_ROW  (N_OBJ * 2)               // 32768 float4 per batch row
#define F4_PER_BLK  (F4_PER_ROW / SPLIT)      // 1024 float4 per block (per stream)
#define UNROLL      4                         // THREADS*UNROLL == F4_PER_BLK

// Partial sums, laid out [b][s] so one warp per batch reads one 128B line.
__device__ float g_partials[B_DIM * SPLIT];

__global__ __launch_bounds__(THREADS, 8)
void label_loss_kernel(const float* __restrict__ pred,
                       const float* __restrict__ gt) {
    const int b = blockIdx.x;
    const int s = blockIdx.y;

    const float4* __restrict__ p =
        reinterpret_cast<const float4*>(pred) + (size_t)b * F4_PER_ROW + s * F4_PER_BLK;
    const float4* __restrict__ g =
        reinterpret_cast<const float4*>(gt)   + (size_t)b * F4_PER_ROW + s * F4_PER_BLK;

    // float4-index parity for this thread is constant (strides even):
    // odd float4 -> its .w is channel 7 (excluded from loss).
    const float wsel = (threadIdx.x & 1) ? 0.0f : 1.0f;

    // One fully-unrolled pass: 4 p + 4 g = 8 front-batched LDG.128 per thread.
    float4 pv[UNROLL], gv[UNROLL];
    #pragma unroll
    for (int u = 0; u < UNROLL; u++) {
        const int idx = u * THREADS + threadIdx.x;
        pv[u] = p[idx];
        gv[u] = g[idx];
    }

    float acc = 0.0f;
    #pragma unroll
    for (int u = 0; u < UNROLL; u++) {
        float d0 = pv[u].x - gv[u].x;
        float d1 = pv[u].y - gv[u].y;
        float d2 = pv[u].z - gv[u].z;
        float d3 = (pv[u].w - gv[u].w) * wsel;   // channel 7 masked on odd lanes
        acc += d0*d0 + d1*d1 + d2*d2 + d3*d3;
    }

    // Warp reduction
    #pragma unroll
    for (int off = 16; off > 0; off >>= 1)
        acc += __shfl_xor_sync(0xFFFFFFFFu, acc, off);

    // Cross-warp reduction via shared memory
    __shared__ float warp_sums[THREADS / 32];
    const int lane = threadIdx.x & 31;
    const int wid  = threadIdx.x >> 5;
    if (lane == 0) warp_sums[wid] = acc;
    __syncthreads();

    if (wid == 0) {
        float v = (lane < THREADS / 32) ? warp_sums[lane] : 0.0f;
        #pragma unroll
        for (int off = 4; off > 0; off >>= 1)
            v += __shfl_xor_sync(0xFFFFFFFFu, v, off);
        if (lane == 0)
            g_partials[b * SPLIT + s] = v;   // plain store, no atomic
    }
}

// One warp per batch: 32 blocks x 256 threads = 256 warps.
__global__ __launch_bounds__(256)
void reduce_partials_kernel(float* __restrict__ out) {
    const int lane = threadIdx.x & 31;
    const int b    = blockIdx.x * 8 + (threadIdx.x >> 5);

    float v = g_partials[b * SPLIT + lane];   // coalesced: one 128B line per warp
    #pragma unroll
    for (int off = 16; off > 0; off >>= 1)
        v += __shfl_xor_sync(0xFFFFFFFFu, v, off);
    if (lane == 0)
        out[b] = v;
}

extern "C" void kernel_launch(void* const* d_in, const int* in_sizes, int n_in,
                              void* d_out, int out_size) {
    const float* pred = (const float*)d_in[0];
    const float* gt   = (const float*)d_in[1];
    float* out        = (float*)d_out;

    dim3 grid(B_DIM, SPLIT);
    label_loss_kernel<<<grid, THREADS>>>(pred, gt);
    reduce_partials_kernel<<<32, 256>>>(out);
}

// round 6
// speedup vs baseline: 1.0419x; 1.0059x over previous
#include <cuda_runtime.h>

// LabelLoss: out[b] = sum_{n,c<7} (pred[b,n,c] - gt[b,n,c])^2
// pred, gt: [256, 16384, 8] fp32. Pure HBM-bound streaming reduction.
//
// R6: SINGLE kernel. Streaming body identical to R3/R5 (fine-grained chunks,
// multi-wave work-stealing, coalesced float4, channel-7 parity mask).
// Cross-chunk reduction fused via the threadFenceReduction ticket pattern:
// the last block to finish for batch b sums the 32 partials and writes
// out[b] directly (overwriting the poison), then resets the ticket counter
// so the kernel is replay-deterministic under graph capture.

#define B_DIM       256
#define N_OBJ       16384
#define THREADS     256
#define SPLIT       32                        // chunks per batch row -> grid 8192
#define F4_PER_ROW  (N_OBJ * 2)               // 32768 float4 per batch row
#define F4_PER_BLK  (F4_PER_ROW / SPLIT)      // 1024 float4 per block (per stream)
#define UNROLL      4                         // THREADS*UNROLL == F4_PER_BLK

// Partial sums [b][s]: the finishing warp reads one 128B line, coalesced.
__device__ float g_partials[B_DIM * SPLIT];
// Ticket counters, one per batch row. Zero-initialized; self-reset each launch.
__device__ unsigned int g_count[B_DIM];

__global__ __launch_bounds__(THREADS, 8)
void label_loss_kernel(const float* __restrict__ pred,
                       const float* __restrict__ gt,
                       float* __restrict__ out) {
    const int b = blockIdx.x;
    const int s = blockIdx.y;

    const float4* __restrict__ p =
        reinterpret_cast<const float4*>(pred) + (size_t)b * F4_PER_ROW + s * F4_PER_BLK;
    const float4* __restrict__ g =
        reinterpret_cast<const float4*>(gt)   + (size_t)b * F4_PER_ROW + s * F4_PER_BLK;

    // float4-index parity for this thread is constant (strides even):
    // odd float4 -> its .w is channel 7 (excluded from loss).
    const float wsel = (threadIdx.x & 1) ? 0.0f : 1.0f;

    // One fully-unrolled pass: 4 p + 4 g = 8 front-batched LDG.128 per thread.
    float4 pv[UNROLL], gv[UNROLL];
    #pragma unroll
    for (int u = 0; u < UNROLL; u++) {
        const int idx = u * THREADS + threadIdx.x;
        pv[u] = p[idx];
        gv[u] = g[idx];
    }

    float acc = 0.0f;
    #pragma unroll
    for (int u = 0; u < UNROLL; u++) {
        float d0 = pv[u].x - gv[u].x;
        float d1 = pv[u].y - gv[u].y;
        float d2 = pv[u].z - gv[u].z;
        float d3 = (pv[u].w - gv[u].w) * wsel;   // channel 7 masked on odd lanes
        acc += d0*d0 + d1*d1 + d2*d2 + d3*d3;
    }

    // Warp reduction
    #pragma unroll
    for (int off = 16; off > 0; off >>= 1)
        acc += __shfl_xor_sync(0xFFFFFFFFu, acc, off);

    // Cross-warp reduction via shared memory
    __shared__ float warp_sums[THREADS / 32];
    const int lane = threadIdx.x & 31;
    const int wid  = threadIdx.x >> 5;
    if (lane == 0) warp_sums[wid] = acc;
    __syncthreads();

    if (wid == 0) {
        float v = (lane < THREADS / 32) ? warp_sums[lane] : 0.0f;
        #pragma unroll
        for (int off = 4; off > 0; off >>= 1)
            v += __shfl_xor_sync(0xFFFFFFFFu, v, off);

        // Publish this block's partial, then take a ticket.
        unsigned int ticket = 0;
        if (lane == 0) {
            g_partials[b * SPLIT + s] = v;
            __threadfence();                       // partial visible before ticket
            ticket = atomicAdd(&g_count[b], 1u);
        }
        ticket = __shfl_sync(0xFFFFFFFFu, ticket, 0);

        // Last block for this batch row reduces all 32 partials.
        if (ticket == SPLIT - 1) {
            float r = g_partials[b * SPLIT + lane];  // one 128B line, L2-hit
            #pragma unroll
            for (int off = 16; off > 0; off >>= 1)
                r += __shfl_xor_sync(0xFFFFFFFFu, r, off);
            if (lane == 0) {
                out[b] = r;
                g_count[b] = 0;                      // reset for next graph replay
            }
        }
    }
}

extern "C" void kernel_launch(void* const* d_in, const int* in_sizes, int n_in,
                              void* d_out, int out_size) {
    const float* pred = (const float*)d_in[0];
    const float* gt   = (const float*)d_in[1];
    float* out        = (float*)d_out;

    dim3 grid(B_DIM, SPLIT);
    label_loss_kernel<<<grid, THREADS>>>(pred, gt, out);
}